// round 15
// baseline (speedup 1.0000x reference)
#include <cuda_runtime.h>
#include <math.h>
#include <stdint.h>

#define BN 4
#define NN 256
#define EFD 256
#define MD 128
#define CLS 600

// ---------------- device scratch (static, zero-init) ----------------
__device__ float g_mraw[(size_t)BN * NN * NN * MD];   // 128 MB
__device__ float g_sA[BN * NN * NN];
__device__ float g_sB[BN * NN * NN];
__device__ float g_nf[BN * NN * MD];
__device__ float g_anf[BN * NN * MD];
__device__ float g_msum[BN * NN * MD];
__device__ float g_WeP[8 * 10240];   // edge B image: [chunk][(kq,ng,g,l)*20 + n*2+h], ng0-1=Wem, ng2-3=Wel
__device__ float g_Wl1P[4 * 6144];   // round B image: [chunk][(kq,ng,g,l)*12 + n*2+h]
__device__ float g_bem[MD];          // b_er @ W_msg_bot
__device__ float g_bel[MD];          // b_er @ W_l1 + b_l1

__device__ __forceinline__ float sigmoidf_(float x) { return 1.0f / (1.0f + __expf(-x)); }

__device__ __forceinline__ float tf32f(float v) {
    uint32_t u;
    asm("cvt.rna.tf32.f32 %0, %1;" : "=r"(u) : "f"(v));
    return __uint_as_float(u);
}

__device__ __forceinline__ void mma8(float* c, const uint32_t* a, const uint32_t* b) {
    asm volatile(
        "mma.sync.aligned.m16n8k8.row.col.f32.tf32.tf32.f32 "
        "{%0,%1,%2,%3}, {%4,%5,%6,%7}, {%8,%9}, {%0,%1,%2,%3};"
        : "+f"(c[0]), "+f"(c[1]), "+f"(c[2]), "+f"(c[3])
        : "r"(a[0]), "r"(a[1]), "r"(a[2]), "r"(a[3]), "r"(b[0]), "r"(b[1]));
}

__device__ __forceinline__ uint32_t smem_u32(const void* p) {
    uint32_t a;
    asm("{ .reg .u64 t; cvta.to.shared.u64 t, %1; cvt.u32.u64 %0, t; }" : "=r"(a) : "l"(p));
    return a;
}
__device__ __forceinline__ void cpa16(uint32_t dst, const float* src) {
    asm volatile("cp.async.cg.shared.global [%0], [%1], 16;" :: "r"(dst), "l"(src));
}
#define CPA_COMMIT() asm volatile("cp.async.commit_group;" ::: "memory")
#define CPA_WAIT0()  asm volatile("cp.async.wait_group 0;" ::: "memory")

// permuted position helpers (host of truth for the layouts)
__device__ __forceinline__ int pos_e(int k, int cc) {     // edge B: k 0..255, cc 0..255
    int chunk = k >> 5, k5 = k & 31;
    int kq = k5 >> 3, h = (k5 >> 2) & 1, l = k5 & 3;
    int ng = cc >> 6, n = (cc >> 3) & 7, g = cc & 7;
    return chunk * 10240 + ((((kq * 4 + ng) * 8 + g) * 4 + l) * 20) + n * 2 + h;
}
__device__ __forceinline__ int pos_r(int k, int c) {      // round B: k 0..127, c 0..127
    int chunk = k >> 5, k5 = k & 31;
    int kq = k5 >> 3, h = (k5 >> 2) & 1, l = k5 & 3;
    int ng = c >> 5, n = (c >> 3) & 3, g = c & 7;
    return chunk * 6144 + ((((kq * 4 + ng) * 8 + g) * 4 + l) * 12) + n * 2 + h;
}
__device__ __forceinline__ int pos_A(int row, int k5) {   // A (both kernels): row 0..63, k5 0..31
    int kq = k5 >> 3, h = (k5 >> 2) & 1, l = k5 & 3;
    int g = row & 7, rh = (row >> 3) & 1, m = (row >> 4) & 1, mg = row >> 5;
    return ((((kq * 2 + mg) * 2 + m) * 8 + g) * 4 + l) * 4 + rh * 2 + h;
}

// ================= prep: zero adj + zero msum + fold weights (permuted) + node features =================
__global__ __launch_bounds__(256) void k_prep(
    float* __restrict__ out,
    const float* __restrict__ nfeat,
    const float* __restrict__ W_er, const float* __restrict__ b_er,
    const float* __restrict__ W_nr, const float* __restrict__ b_nr,
    const float* __restrict__ W_msg, const float* __restrict__ b_msg,
    const float* __restrict__ W_l1, const float* __restrict__ b_l1)
{
    const int t = threadIdx.x;
    const int blk = blockIdx.x;
    __shared__ float xs[4][EFD];
    __shared__ float nfs[4][MD];
    __shared__ float part[2][4][MD];

    if (blk < 256) {                       // zero pred_adj region (1 MB)
        int idx = blk * 256 + t;
        reinterpret_cast<float4*>(out)[idx] = make_float4(0.f, 0.f, 0.f, 0.f);
    } else if (blk < 384) {                // zero g_msum (512 KB)
        int idx = (blk - 256) * 256 + t;
        reinterpret_cast<float4*>(g_msum)[idx] = make_float4(0.f, 0.f, 0.f, 0.f);
    } else if (blk < 641) {                // fold, k-split across halves
        const int k = blk - 384;           // 0..256
        const int c = t & 127;
        const int h = t >> 7;
        float am = 0.f, al = 0.f;
        if (k < EFD) {
            #pragma unroll 8
            for (int j = h * 64; j < h * 64 + 64; j++) {
                float a = W_er[k * MD + j];
                am = fmaf(a, W_msg[(MD + j) * MD + c], am);
                al = fmaf(a, W_l1[j * MD + c], al);
            }
        } else {
            #pragma unroll 8
            for (int j = h * 64; j < h * 64 + 64; j++) {
                float a = b_er[j];
                am = fmaf(a, W_msg[(MD + j) * MD + c], am);
                al = fmaf(a, W_l1[j * MD + c], al);
            }
        }
        part[h][0][c] = am;
        part[h][1][c] = al;
        __syncthreads();
        if (h == 0) {
            float amt = part[0][0][c] + part[1][0][c];
            float alt = part[0][1][c] + part[1][1][c];
            if (k < EFD) {
                g_WeP[pos_e(k, c)]       = tf32f(amt);   // Wem -> cols 0..127
                g_WeP[pos_e(k, 128 + c)] = tf32f(alt);   // Wel -> cols 128..255
                if (k < MD)
                    g_Wl1P[pos_r(k, c)] = tf32f(W_l1[k * MD + c]);
            } else {
                g_bem[c] = amt;
                g_bel[c] = alt + b_l1[c];
            }
        }
    } else {                               // node features: 4 nodes, k-split halves
        const int g0 = (blk - 641) * 4;
        const int c = t & 127;
        const int h = t >> 7;
        {
            const float4* src = reinterpret_cast<const float4*>(nfeat + (size_t)g0 * EFD);
            reinterpret_cast<float4*>(&xs[0][0])[t] = src[t];
        }
        __syncthreads();
        float acc[4] = {0.f, 0.f, 0.f, 0.f};
        #pragma unroll 8
        for (int k = h * 128; k < h * 128 + 128; k++) {
            float wv = W_nr[k * MD + c];
            #pragma unroll
            for (int n = 0; n < 4; n++) acc[n] = fmaf(xs[n][k], wv, acc[n]);
        }
        #pragma unroll
        for (int n = 0; n < 4; n++) part[h][n][c] = acc[n];
        __syncthreads();
        if (h == 0) {
            float bv = b_nr[c];
            #pragma unroll
            for (int n = 0; n < 4; n++) {
                float v = part[0][n][c] + part[1][n][c] + bv;
                nfs[n][c] = v;
                g_nf[(size_t)(g0 + n) * MD + c] = v;
            }
        }
        __syncthreads();
        float acc2[4] = {0.f, 0.f, 0.f, 0.f};
        #pragma unroll 8
        for (int k = h * 64; k < h * 64 + 64; k++) {
            float wv = W_msg[k * MD + c];
            #pragma unroll
            for (int n = 0; n < 4; n++) acc2[n] = fmaf(nfs[n][k], wv, acc2[n]);
        }
        #pragma unroll
        for (int n = 0; n < 4; n++) part[h][n][c] = acc2[n];
        __syncthreads();
        if (h == 0) {
            float bv = b_msg[c];
            #pragma unroll
            for (int n = 0; n < 4; n++)
                g_anf[(size_t)(g0 + n) * MD + c] = part[0][n][c] + part[1][n][c] + bv;
        }
    }
}

// ================= edge kernel: permuted frags + double-buffered pipeline =================
// smem: A 2x2048f @0 (16384B) | B 2x10240f @16384 (81920B) | bem @98304 | bel @98816 | u @99328 | lpart @99840
#define ED_SMEM 100352
__global__ __launch_bounds__(256, 2) void k_edge_mma(
    const float* __restrict__ X,
    const int* __restrict__ hn, const int* __restrict__ on,
    const float* __restrict__ W_l2, const float* __restrict__ b_l2)
{
    const int b  = blockIdx.z;
    const int V  = hn[b] + on[b];
    const int i0 = blockIdx.y * 4;
    const int w0 = blockIdx.x * 16;
    if (i0 >= V || w0 >= V) return;

    extern __shared__ char sm_[];
    float* Asm   = (float*)sm_;                    // [2][2048]
    float* Bsm   = (float*)(sm_ + 16384);          // [2][10240]
    float* bem_s = (float*)(sm_ + 98304);
    float* bel_s = (float*)(sm_ + 98816);
    float* u_s   = (float*)(sm_ + 99328);
    float* lpart = (float*)(sm_ + 99840);          // [2][64]

    const int t    = threadIdx.x;
    const int wid  = t >> 5;
    const int lane = t & 31;
    const int g    = lane >> 2;
    const int l    = lane & 3;
    const int mg   = wid >> 2;             // 0..1
    const int ng   = wid & 3;              // 0..3

    if (t < 128) { bem_s[t] = g_bem[t]; bel_s[t] = g_bel[t]; u_s[t] = W_l2[t]; }

    const int arow  = t >> 2;              // 0..63
    const int apart = t & 3;               // k-quarter (kq for A fill)
    const int ari = arow >> 4, awi = arow & 15;
    const float* xrow = X + (size_t)((b * NN + i0 + ari) * NN + w0 + awi) * EFD + apart * 8;
    int aposw[8];
    #pragma unroll
    for (int j = 0; j < 8; j++) aposw[j] = pos_A(arow, apart * 8 + j);

    const uint32_t bdst0 = smem_u32(Bsm) + (uint32_t)t * 16;   // idx=jj*256+t float4s
    const float* bsrc0 = g_WeP + (size_t)t * 4;

    float acc[2][8][4];
    #pragma unroll
    for (int m = 0; m < 2; m++)
        #pragma unroll
        for (int n = 0; n < 8; n++)
            #pragma unroll
            for (int q = 0; q < 4; q++) acc[m][n][q] = 0.f;

    float ar[8];
    // ---- prologue: chunk 0 ----
    {
        float4 v0 = *(const float4*)(xrow);
        float4 v1 = *(const float4*)(xrow + 4);
        ar[0]=v0.x; ar[1]=v0.y; ar[2]=v0.z; ar[3]=v0.w;
        ar[4]=v1.x; ar[5]=v1.y; ar[6]=v1.z; ar[7]=v1.w;
        #pragma unroll
        for (int jj = 0; jj < 10; jj++)
            cpa16(bdst0 + jj * 4096, bsrc0 + (size_t)jj * 1024);
        CPA_COMMIT();
        #pragma unroll
        for (int jj = 0; jj < 8; jj++) Asm[aposw[jj]] = tf32f(ar[jj]);
        CPA_WAIT0();
    }
    __syncthreads();

    #pragma unroll 1
    for (int kc = 0; kc < 8; kc++) {
        const int cur = kc & 1, nxt = cur ^ 1;
        if (kc < 7) {
            #pragma unroll
            for (int jj = 0; jj < 10; jj++)
                cpa16(bdst0 + nxt * 40960u + jj * 4096,
                      bsrc0 + (size_t)(kc + 1) * 10240 + (size_t)jj * 1024);
            CPA_COMMIT();
            float4 v0 = *(const float4*)(xrow + (kc + 1) * 32);
            float4 v1 = *(const float4*)(xrow + (kc + 1) * 32 + 4);
            ar[0]=v0.x; ar[1]=v0.y; ar[2]=v0.z; ar[3]=v0.w;
            ar[4]=v1.x; ar[5]=v1.y; ar[6]=v1.z; ar[7]=v1.w;
        }
        const float* Ac = Asm + cur * 2048;
        const float* Bc = Bsm + cur * 10240;
        #pragma unroll
        for (int kq = 0; kq < 4; kq++) {
            uint32_t af[2][4];
            #pragma unroll
            for (int m = 0; m < 2; m++) {
                float4 a4 = *(const float4*)(Ac + ((((kq * 2 + mg) * 2 + m) * 8 + g) * 4 + l) * 4);
                af[m][0] = __float_as_uint(a4.x);   // (rh0,h0)
                af[m][1] = __float_as_uint(a4.z);   // (rh1,h0)
                af[m][2] = __float_as_uint(a4.y);   // (rh0,h1)
                af[m][3] = __float_as_uint(a4.w);   // (rh1,h1)
            }
            const float* bb = Bc + (((kq * 4 + ng) * 8 + g) * 4 + l) * 20;
            float4 b0 = *(const float4*)(bb);
            float4 b1 = *(const float4*)(bb + 4);
            float4 b2 = *(const float4*)(bb + 8);
            float4 b3 = *(const float4*)(bb + 12);
            float r[16] = {b0.x,b0.y,b0.z,b0.w, b1.x,b1.y,b1.z,b1.w,
                           b2.x,b2.y,b2.z,b2.w, b3.x,b3.y,b3.z,b3.w};
            #pragma unroll
            for (int n = 0; n < 8; n++) {
                uint32_t bf[2] = { __float_as_uint(r[n*2]), __float_as_uint(r[n*2+1]) };
                mma8(acc[0][n], af[0], bf);
                mma8(acc[1][n], af[1], bf);
            }
        }
        if (kc < 7) {
            float* An = Asm + nxt * 2048;
            #pragma unroll
            for (int jj = 0; jj < 8; jj++) An[aposw[jj]] = tf32f(ar[jj]);
            CPA_WAIT0();
        }
        __syncthreads();
    }

    const float bl2v = b_l2[0];
    if (ng >= 2) {
        float p[4] = {0.f, 0.f, 0.f, 0.f};
        #pragma unroll
        for (int m = 0; m < 2; m++)
            #pragma unroll
            for (int n = 0; n < 8; n++) {
                int cb = (ng - 2) * 64 + n * 8 + 2 * l;
                float u0 = u_s[cb], u1 = u_s[cb + 1];
                float e0 = bel_s[cb], e1 = bel_s[cb + 1];
                p[m*2+0] += fmaxf(acc[m][n][0] + e0, 0.f) * u0 + fmaxf(acc[m][n][1] + e1, 0.f) * u1;
                p[m*2+1] += fmaxf(acc[m][n][2] + e0, 0.f) * u0 + fmaxf(acc[m][n][3] + e1, 0.f) * u1;
            }
        #pragma unroll
        for (int q = 0; q < 4; q++) {
            p[q] += __shfl_xor_sync(0xffffffffu, p[q], 1);
            p[q] += __shfl_xor_sync(0xffffffffu, p[q], 2);
        }
        if (l == 0) {
            lpart[(ng - 2) * 64 + mg * 32 + g]      = p[0];
            lpart[(ng - 2) * 64 + mg * 32 + g + 8]  = p[1];
            lpart[(ng - 2) * 64 + mg * 32 + 16 + g] = p[2];
            lpart[(ng - 2) * 64 + mg * 32 + 24 + g] = p[3];
        }
    } else {
        float* mst = Bsm;                  // scratch [64][132]
        #pragma unroll
        for (int m = 0; m < 2; m++) {
            int r0 = mg * 32 + m * 16 + g;
            #pragma unroll
            for (int n = 0; n < 8; n++) {
                int cb = ng * 64 + n * 8 + 2 * l;
                mst[r0 * 132 + cb]           = acc[m][n][0];
                mst[r0 * 132 + cb + 1]       = acc[m][n][1];
                mst[(r0 + 8) * 132 + cb]     = acc[m][n][2];
                mst[(r0 + 8) * 132 + cb + 1] = acc[m][n][3];
            }
        }
    }
    __syncthreads();

    if (t < 64) {
        int ri2 = t >> 4, wi2 = t & 15;
        if (i0 + ri2 < V && w0 + wi2 < V)
            g_sA[(b * NN + i0 + ri2) * NN + w0 + wi2] = lpart[t] + lpart[64 + t] + bl2v;
    }
    {
        int row = t >> 2, part = t & 3;
        int ri2 = row >> 4, wi2 = row & 15;
        if (i0 + ri2 < V && w0 + wi2 < V) {
            const float* ap = g_anf + (size_t)(b * NN + w0 + wi2) * MD + part * 32;
            float* mp = g_mraw + (size_t)((b * NN + i0 + ri2) * NN + w0 + wi2) * MD + part * 32;
            const float* mst = Bsm + row * 132 + part * 32;
            #pragma unroll
            for (int jj = 0; jj < 8; jj++) {
                float4 m4 = *(const float4*)(mst + jj * 4);
                float4 a4 = *(const float4*)(ap + jj * 4);
                float4 e4 = *(const float4*)(&bem_s[part * 32 + jj * 4]);
                float4 v;
                v.x = fmaxf(m4.x + e4.x + a4.x, 0.f);
                v.y = fmaxf(m4.y + e4.y + a4.y, 0.f);
                v.z = fmaxf(m4.z + e4.z + a4.z, 0.f);
                v.w = fmaxf(m4.w + e4.w + a4.w, 0.f);
                *(float4*)(mp + jj * 4) = v;
            }
        }
    }
}

// ================= round kernel: permuted frags, occ 3, fused msum on pass 2 =================
__global__ __launch_bounds__(256, 3) void k_round_mma(
    int pass,
    const int* __restrict__ hn, const int* __restrict__ on,
    const float* __restrict__ b_l1,
    const float* __restrict__ W_l2, const float* __restrict__ b_l2,
    float* __restrict__ out_adj)
{
    const int b  = blockIdx.z;
    const int V  = hn[b] + on[b];
    const int i0 = blockIdx.y * 4;
    const int w0 = blockIdx.x * 16;
    if (i0 >= V || w0 >= V) return;

    const float* sprev = (pass == 1) ? g_sA : g_sB;
    float*       snext = (pass == 1) ? g_sB : g_sA;

    __shared__ float Asm[2][2048];         // 16 KB
    __shared__ float Bsm[2][6144];         // 48 KB
    __shared__ float lpart[4][64];
    __shared__ float gates[64];
    __shared__ float bl1_s[MD], u_s[MD];

    const int t    = threadIdx.x;
    const int wid  = t >> 5;
    const int lane = t & 31;
    const int g    = lane >> 2;
    const int l    = lane & 3;
    const int mg   = wid >> 2;
    const int ng   = wid & 3;

    if (t < 128) { bl1_s[t] = b_l1[t]; u_s[t] = W_l2[t]; }
    if (t < 64) {
        int ri = t >> 4, wi = t & 15;
        bool ok = (i0 + ri < V) && (w0 + wi < V);
        gates[t] = ok ? sigmoidf_(sprev[(b * NN + w0 + wi) * NN + i0 + ri]) : 0.f;
    }
    __syncthreads();

    const int arow  = t >> 2;
    const int apart = t & 3;
    const int ari = arow >> 4, awi = arow & 15;
    const float gv = gates[arow];
    const float* mrow = g_mraw + (size_t)((b * NN + w0 + awi) * NN + i0 + ari) * MD + apart * 8;
    int aposw[8];
    #pragma unroll
    for (int j = 0; j < 8; j++) aposw[j] = pos_A(arow, apart * 8 + j);

    const uint32_t bdst0 = smem_u32(&Bsm[0][0]) + (uint32_t)t * 16;
    const float* bsrc0 = g_Wl1P + (size_t)t * 4;

    float acc[2][4][4];
    #pragma unroll
    for (int m = 0; m < 2; m++)
        #pragma unroll
        for (int n = 0; n < 4; n++)
            #pragma unroll
            for (int q = 0; q < 4; q++) acc[m][n][q] = 0.f;

    float ar[8];
    #pragma unroll
    for (int jj = 0; jj < 8; jj++) ar[jj] = mrow[jj];
    #pragma unroll
    for (int jj = 0; jj < 6; jj++)
        cpa16(bdst0 + jj * 4096, bsrc0 + (size_t)jj * 1024);
    CPA_COMMIT();
    #pragma unroll
    for (int jj = 0; jj < 8; jj++) Asm[0][aposw[jj]] = tf32f(ar[jj] * gv);
    CPA_WAIT0();
    __syncthreads();

    #pragma unroll 1
    for (int kc = 0; kc < 4; kc++) {
        const int cur = kc & 1, nxt = cur ^ 1;
        if (kc < 3) {
            #pragma unroll
            for (int jj = 0; jj < 6; jj++)
                cpa16(bdst0 + nxt * 24576u + jj * 4096,
                      bsrc0 + (size_t)(kc + 1) * 6144 + (size_t)jj * 1024);
            CPA_COMMIT();
            #pragma unroll
            for (int jj = 0; jj < 8; jj++) ar[jj] = mrow[(kc + 1) * 32 + jj];
        }
        const float* Ac = Asm[cur];
        const float* Bc = Bsm[cur];
        #pragma unroll
        for (int kq = 0; kq < 4; kq++) {
            uint32_t af[2][4];
            #pragma unroll
            for (int m = 0; m < 2; m++) {
                float4 a4 = *(const float4*)(Ac + ((((kq * 2 + mg) * 2 + m) * 8 + g) * 4 + l) * 4);
                af[m][0] = __float_as_uint(a4.x);
                af[m][1] = __float_as_uint(a4.z);
                af[m][2] = __float_as_uint(a4.y);
                af[m][3] = __float_as_uint(a4.w);
            }
            const float* bb = Bc + (((kq * 4 + ng) * 8 + g) * 4 + l) * 12;
            float4 b0 = *(const float4*)(bb);
            float4 b1 = *(const float4*)(bb + 4);
            float r[8] = {b0.x,b0.y,b0.z,b0.w, b1.x,b1.y,b1.z,b1.w};
            #pragma unroll
            for (int n = 0; n < 4; n++) {
                uint32_t bf[2] = { __float_as_uint(r[n*2]), __float_as_uint(r[n*2+1]) };
                mma8(acc[0][n], af[0], bf);
                mma8(acc[1][n], af[1], bf);
            }
        }
        if (kc < 3) {
            #pragma unroll
            for (int jj = 0; jj < 8; jj++) Asm[nxt][aposw[jj]] = tf32f(ar[jj] * gv);
            CPA_WAIT0();
        }
        __syncthreads();
    }

    {
        float p[4] = {0.f, 0.f, 0.f, 0.f};
        #pragma unroll
        for (int m = 0; m < 2; m++)
            #pragma unroll
            for (int n = 0; n < 4; n++) {
                int cb = ng * 32 + n * 8 + 2 * l;
                float u0 = u_s[cb], u1 = u_s[cb + 1];
                float e0 = bl1_s[cb], e1 = bl1_s[cb + 1];
                p[m*2+0] += fmaxf(acc[m][n][0] + e0, 0.f) * u0 + fmaxf(acc[m][n][1] + e1, 0.f) * u1;
                p[m*2+1] += fmaxf(acc[m][n][2] + e0, 0.f) * u0 + fmaxf(acc[m][n][3] + e1, 0.f) * u1;
            }
        #pragma unroll
        for (int q = 0; q < 4; q++) {
            p[q] += __shfl_xor_sync(0xffffffffu, p[q], 1);
            p[q] += __shfl_xor_sync(0xffffffffu, p[q], 2);
        }
        if (l == 0) {
            lpart[ng][mg * 32 + g]      = p[0];
            lpart[ng][mg * 32 + g + 8]  = p[1];
            lpart[ng][mg * 32 + 16 + g] = p[2];
            lpart[ng][mg * 32 + 24 + g] = p[3];
        }
    }
    __syncthreads();
    if (t < 64) {
        int ri2 = t >> 4, wi2 = t & 15;
        bool ok = (i0 + ri2 < V) && (w0 + wi2 < V);
        float sv = 0.f;
        if (ok) {
            int d = (b * NN + i0 + ri2) * NN + w0 + wi2;
            sv = (lpart[0][t] + lpart[1][t]) + (lpart[2][t] + lpart[3][t]) + b_l2[0];
            snext[d] = sv;
            if (out_adj) out_adj[d] = sv;
        }
        gates[t] = ok ? sigmoidf_(sv) : 0.f;
    }

    // ---- fused m_sum on final pass ----
    if (out_adj) {
        __syncthreads();
        const int r = t >> 6;
        const int c = (t & 63) * 2;
        if (i0 + r < V) {
            const float* mp2 = g_mraw + (size_t)((b * NN + i0 + r) * NN + w0) * MD + c;
            float s0 = 0.f, s1 = 0.f;
            #pragma unroll
            for (int wq = 0; wq < 16; wq++) {
                float gq = gates[r * 16 + wq];
                float2 mv = *(const float2*)(mp2 + (size_t)wq * MD);
                s0 = fmaf(gq, mv.x, s0);
                s1 = fmaf(gq, mv.y, s1);
            }
            float* dst = &g_msum[(size_t)(b * NN + i0 + r) * MD + c];
            atomicAdd(dst, s0);
            atomicAdd(dst + 1, s1);
        }
    }
}

// ---------------- GRU + readout, 4 nodes per block, labels split over blockIdx.z ----------------
__global__ __launch_bounds__(128) void k_gru(
    const int* __restrict__ hn, const int* __restrict__ on,
    const float* __restrict__ W_ih, const float* __restrict__ b_ih,
    const float* __restrict__ W_hh, const float* __restrict__ b_hh,
    const float* __restrict__ W_ro, const float* __restrict__ b_ro,
    float* __restrict__ out)
{
    const int b  = blockIdx.y;
    const int V  = hn[b] + on[b];
    const int i0 = blockIdx.x * 4;
    const int cb = blockIdx.z;
    const int t  = threadIdx.x;

    __shared__ float ms[4][MD];
    __shared__ float hsn[4][MD];
    __shared__ float hnew[4][MD];

    #pragma unroll
    for (int n = 0; n < 4; n++) {
        ms[n][t]  = g_msum[(size_t)(b * NN + i0 + n) * MD + t];
        hsn[n][t] = g_nf[(size_t)(b * NN + i0 + n) * MD + t];
    }
    __syncthreads();

    float air[4], aiz[4], ain[4], ahr[4], ahz[4], ahn[4];
    {
        float bir = b_ih[t], biz = b_ih[128 + t], bin_ = b_ih[256 + t];
        float bhr = b_hh[t], bhz = b_hh[128 + t], bhn = b_hh[256 + t];
        #pragma unroll
        for (int n = 0; n < 4; n++) {
            air[n] = bir; aiz[n] = biz; ain[n] = bin_;
            ahr[n] = bhr; ahz[n] = bhz; ahn[n] = bhn;
        }
    }
    #pragma unroll 2
    for (int k = 0; k < MD; k++) {
        float wr = W_ih[k * 384 + t];
        float wz = W_ih[k * 384 + 128 + t];
        float wn = W_ih[k * 384 + 256 + t];
        float vr = W_hh[k * 384 + t];
        float vz = W_hh[k * 384 + 128 + t];
        float vn = W_hh[k * 384 + 256 + t];
        #pragma unroll
        for (int n = 0; n < 4; n++) {
            float xv = ms[n][k], hv = hsn[n][k];
            air[n] = fmaf(xv, wr, air[n]);
            aiz[n] = fmaf(xv, wz, aiz[n]);
            ain[n] = fmaf(xv, wn, ain[n]);
            ahr[n] = fmaf(hv, vr, ahr[n]);
            ahz[n] = fmaf(hv, vz, ahz[n]);
            ahn[n] = fmaf(hv, vn, ahn[n]);
        }
    }
    #pragma unroll
    for (int n = 0; n < 4; n++) {
        float r   = sigmoidf_(air[n] + ahr[n]);
        float z   = sigmoidf_(aiz[n] + ahz[n]);
        float nn_ = tanhf(ain[n] + r * ahn[n]);
        hnew[n][t] = (1.f - z) * nn_ + z * hsn[n][t];
    }
    __syncthreads();

    float* lab = out + (size_t)BN * NN * NN;
    int c = cb * 128 + t;
    if (c < CLS) {
        float lacc[4];
        #pragma unroll
        for (int n = 0; n < 4; n++) lacc[n] = 0.f;
        #pragma unroll 4
        for (int k = 0; k < MD; k++) {
            float wv = W_ro[k * CLS + c];
            #pragma unroll
            for (int n = 0; n < 4; n++) lacc[n] = fmaf(hnew[n][k], wv, lacc[n]);
        }
        float bv = b_ro[c];
        #pragma unroll
        for (int n = 0; n < 4; n++) {
            int i = i0 + n;
            float v = (i < V) ? (lacc[n] + bv) : 0.f;
            lab[(size_t)(b * NN + i) * CLS + c] = v;
        }
    }
}

// ---------------- launcher ----------------
extern "C" void kernel_launch(void* const* d_in, const int* in_sizes, int n_in,
                              void* d_out, int out_size)
{
    const float* edge_features = (const float*)d_in[0];
    const float* node_features = (const float*)d_in[1];
    const int*   human = (const int*)d_in[4];
    const int*   obj   = (const int*)d_in[5];
    const float* W_er  = (const float*)d_in[6];
    const float* b_er  = (const float*)d_in[7];
    const float* W_nr  = (const float*)d_in[8];
    const float* b_nr  = (const float*)d_in[9];
    const float* W_l1  = (const float*)d_in[10];
    const float* b_l1  = (const float*)d_in[11];
    const float* W_l2  = (const float*)d_in[12];
    const float* b_l2  = (const float*)d_in[13];
    const float* W_msg = (const float*)d_in[14];
    const float* b_msg = (const float*)d_in[15];
    const float* W_ih  = (const float*)d_in[16];
    const float* b_ih  = (const float*)d_in[17];
    const float* W_hh  = (const float*)d_in[18];
    const float* b_hh  = (const float*)d_in[19];
    const float* W_ro  = (const float*)d_in[20];
    const float* b_ro  = (const float*)d_in[21];
    float* out = (float*)d_out;

    cudaFuncSetAttribute(k_edge_mma, cudaFuncAttributeMaxDynamicSharedMemorySize, ED_SMEM);

    k_prep<<<897, 256>>>(out, node_features, W_er, b_er, W_nr, b_nr, W_msg, b_msg, W_l1, b_l1);

    dim3 eg(NN / 16, NN / 4, BN);
    k_edge_mma<<<eg, 256, ED_SMEM>>>(edge_features, human, obj, W_l2, b_l2);
    k_round_mma<<<eg, 256>>>(1, human, obj, b_l1, W_l2, b_l2, nullptr);
    k_round_mma<<<eg, 256>>>(2, human, obj, b_l1, W_l2, b_l2, out);

    k_gru<<<dim3(NN / 4, BN, 5), 128>>>(human, obj, W_ih, b_ih, W_hh, b_hh, W_ro, b_ro, out);
}

// round 16
// speedup vs baseline: 1.2710x; 1.2710x over previous
#include <cuda_runtime.h>
#include <math.h>
#include <stdint.h>

#define BN 4
#define NN 256
#define EFD 256
#define MD 128
#define CLS 600

// ---------------- device scratch (static, zero-init) ----------------
__device__ float g_mraw[(size_t)BN * NN * NN * MD];   // 128 MB
__device__ float g_sA[BN * NN * NN];
__device__ float g_sB[BN * NN * NN];
__device__ float g_nf[BN * NN * MD];
__device__ float g_anf[BN * NN * MD];
__device__ float g_msum[BN * NN * MD];
__device__ float g_Wem[EFD * MD];   // tf32(W_er @ W_msg_bot), row-major [k][c]
__device__ float g_Wel[EFD * MD];   // tf32(W_er @ W_l1)
__device__ float g_Wl1c[MD * MD];   // tf32(W_l1)
__device__ float g_bem[MD];         // b_er @ W_msg_bot
__device__ float g_bel[MD];         // b_er @ W_l1 + b_l1

__device__ __forceinline__ float sigmoidf_(float x) { return 1.0f / (1.0f + __expf(-x)); }

__device__ __forceinline__ float tf32f(float v) {
    uint32_t u;
    asm("cvt.rna.tf32.f32 %0, %1;" : "=r"(u) : "f"(v));
    return __uint_as_float(u);
}

__device__ __forceinline__ void mma8(float* c, const uint32_t* a, const uint32_t* b) {
    asm volatile(
        "mma.sync.aligned.m16n8k8.row.col.f32.tf32.tf32.f32 "
        "{%0,%1,%2,%3}, {%4,%5,%6,%7}, {%8,%9}, {%0,%1,%2,%3};"
        : "+f"(c[0]), "+f"(c[1]), "+f"(c[2]), "+f"(c[3])
        : "r"(a[0]), "r"(a[1]), "r"(a[2]), "r"(a[3]), "r"(b[0]), "r"(b[1]));
}

__device__ __forceinline__ uint32_t smem_u32(const void* p) {
    uint32_t a;
    asm("{ .reg .u64 t; cvta.to.shared.u64 t, %1; cvt.u32.u64 %0, t; }" : "=r"(a) : "l"(p));
    return a;
}
__device__ __forceinline__ void cpa16(uint32_t dst, const float* src) {
    asm volatile("cp.async.cg.shared.global [%0], [%1], 16;" :: "r"(dst), "l"(src));
}
#define CPA_COMMIT() asm volatile("cp.async.commit_group;" ::: "memory")
#define CPA_WAIT0()  asm volatile("cp.async.wait_group 0;" ::: "memory")

// ================= prep: zero adj + zero msum + fold (2x c-split, 4x k-split) + nodes (2/block) =================
// blocks: [0,256) zero adj, [256,384) zero msum, [384,898) fold, [898,1410) nodes
__global__ __launch_bounds__(256) void k_prep(
    float* __restrict__ out,
    const float* __restrict__ nfeat,
    const float* __restrict__ W_er, const float* __restrict__ b_er,
    const float* __restrict__ W_nr, const float* __restrict__ b_nr,
    const float* __restrict__ W_msg, const float* __restrict__ b_msg,
    const float* __restrict__ W_l1, const float* __restrict__ b_l1)
{
    const int t = threadIdx.x;
    const int blk = blockIdx.x;
    __shared__ float xs[2][EFD];           // 2 KB
    __shared__ float nfs[2][MD];           // 1 KB
    __shared__ float part4[4][2][64];      // 2 KB (fold)
    __shared__ float partn[2][2][MD];      // 2 KB (nodes)

    if (blk < 256) {                       // zero pred_adj region (1 MB)
        int idx = blk * 256 + t;
        reinterpret_cast<float4*>(out)[idx] = make_float4(0.f, 0.f, 0.f, 0.f);
    } else if (blk < 384) {                // zero g_msum (512 KB)
        int idx = (blk - 256) * 256 + t;
        reinterpret_cast<float4*>(g_msum)[idx] = make_float4(0.f, 0.f, 0.f, 0.f);
    } else if (blk < 898) {                // fold: 2 blocks per k-row, 4-way k-split
        const int f  = blk - 384;          // 0..513
        const int k  = f >> 1;             // 0..256
        const int c  = (f & 1) * 64 + (t & 63);
        const int h  = t >> 6;             // 0..3
        const int j0 = h * 32;
        float am = 0.f, al = 0.f;
        if (k < EFD) {
            #pragma unroll 8
            for (int j = j0; j < j0 + 32; j++) {
                float a = W_er[k * MD + j];
                am = fmaf(a, W_msg[(MD + j) * MD + c], am);
                al = fmaf(a, W_l1[j * MD + c], al);
            }
        } else {
            #pragma unroll 8
            for (int j = j0; j < j0 + 32; j++) {
                float a = b_er[j];
                am = fmaf(a, W_msg[(MD + j) * MD + c], am);
                al = fmaf(a, W_l1[j * MD + c], al);
            }
        }
        part4[h][0][t & 63] = am;
        part4[h][1][t & 63] = al;
        __syncthreads();
        if (h == 0) {
            int cl = t & 63;
            float amt = (part4[0][0][cl] + part4[1][0][cl]) + (part4[2][0][cl] + part4[3][0][cl]);
            float alt = (part4[0][1][cl] + part4[1][1][cl]) + (part4[2][1][cl] + part4[3][1][cl]);
            if (k < EFD) {
                g_Wem[k * MD + c] = tf32f(amt);
                g_Wel[k * MD + c] = tf32f(alt);
                if (k < MD) g_Wl1c[k * MD + c] = tf32f(W_l1[k * MD + c]);
            } else {
                g_bem[c] = amt;
                g_bel[c] = alt + b_l1[c];
            }
        }
    } else {                               // node features: 2 nodes per block, 2-way k-split
        const int g0 = (blk - 898) * 2;
        const int c = t & 127;
        const int h = t >> 7;
        if (t < 128) {
            const float4* src = reinterpret_cast<const float4*>(nfeat + (size_t)g0 * EFD);
            reinterpret_cast<float4*>(&xs[0][0])[t] = src[t];   // 2 rows x 256 floats
        }
        __syncthreads();
        float acc[2] = {0.f, 0.f};
        #pragma unroll 8
        for (int k = h * 128; k < h * 128 + 128; k++) {
            float wv = W_nr[k * MD + c];
            acc[0] = fmaf(xs[0][k], wv, acc[0]);
            acc[1] = fmaf(xs[1][k], wv, acc[1]);
        }
        partn[h][0][c] = acc[0];
        partn[h][1][c] = acc[1];
        __syncthreads();
        if (h == 0) {
            float bv = b_nr[c];
            #pragma unroll
            for (int n = 0; n < 2; n++) {
                float v = partn[0][n][c] + partn[1][n][c] + bv;
                nfs[n][c] = v;
                g_nf[(size_t)(g0 + n) * MD + c] = v;
            }
        }
        __syncthreads();
        float acc2[2] = {0.f, 0.f};
        #pragma unroll 8
        for (int k = h * 64; k < h * 64 + 64; k++) {
            float wv = W_msg[k * MD + c];   // top half rows of W_msg
            acc2[0] = fmaf(nfs[0][k], wv, acc2[0]);
            acc2[1] = fmaf(nfs[1][k], wv, acc2[1]);
        }
        partn[h][0][c] = acc2[0];
        partn[h][1][c] = acc2[1];
        __syncthreads();
        if (h == 0) {
            float bv = b_msg[c];
            #pragma unroll
            for (int n = 0; n < 2; n++)
                g_anf[(size_t)(g0 + n) * MD + c] = partn[0][n][c] + partn[1][n][c] + bv;
        }
    }
}

// ================= edge kernel: tf32 mma.sync, double-buffered pipeline (R14 exact) =================
#define AP 36
#define BP 264
#define ED_SMEM 88064
__global__ __launch_bounds__(256, 2) void k_edge_mma(
    const float* __restrict__ X,
    const int* __restrict__ hn, const int* __restrict__ on,
    const float* __restrict__ W_l2, const float* __restrict__ b_l2)
{
    const int b  = blockIdx.z;
    const int V  = hn[b] + on[b];
    const int i0 = blockIdx.y * 4;
    const int w0 = blockIdx.x * 16;
    if (i0 >= V || w0 >= V) return;

    extern __shared__ char sm_[];
    float* Asb   = (float*)sm_;                    // [2][64][AP]
    float* Bsb   = (float*)(sm_ + 18432);          // [2][32][BP]
    float* bem_s = (float*)(sm_ + 86016);
    float* bel_s = bem_s + 128;
    float* u_s   = bem_s + 256;
    float* lpart = bem_s + 384;                    // [2][64]

    const int t    = threadIdx.x;
    const int wid  = t >> 5;
    const int lane = t & 31;
    const int g    = lane >> 2;
    const int l    = lane & 3;
    const int mg   = wid >> 2;             // 0..1
    const int ng   = wid & 3;              // 0..3

    if (t < 128) { bem_s[t] = g_bem[t]; bel_s[t] = g_bel[t]; u_s[t] = W_l2[t]; }

    const int arow  = t >> 2;              // 0..63 (A fill row)
    const int apart = t & 3;
    const int ari = arow >> 4, awi = arow & 15;
    const float* xrow = X + (size_t)((b * NN + i0 + ari) * NN + w0 + awi) * EFD + apart * 8;
    const uint32_t bbuf = (uint32_t)(32 * BP * 4);
    const uint32_t brow0 = (uint32_t)(t >> 6);
    const uint32_t bc4   = (uint32_t)(t & 63);
    const uint32_t bdst0 = smem_u32(&Bsb[(size_t)brow0 * BP + bc4 * 4]);
    const float* bsrc0 = (bc4 < 32) ? (g_Wem + (size_t)brow0 * MD + bc4 * 4)
                                    : (g_Wel + (size_t)brow0 * MD + (bc4 - 32) * 4);

    float acc[2][8][4];
    #pragma unroll
    for (int m = 0; m < 2; m++)
        #pragma unroll
        for (int n = 0; n < 8; n++)
            #pragma unroll
            for (int q = 0; q < 4; q++) acc[m][n][q] = 0.f;

    float ar[8];
    // ---- prologue: chunk 0 ----
    {
        float4 v0 = *(const float4*)(xrow);
        float4 v1 = *(const float4*)(xrow + 4);
        ar[0]=v0.x; ar[1]=v0.y; ar[2]=v0.z; ar[3]=v0.w;
        ar[4]=v1.x; ar[5]=v1.y; ar[6]=v1.z; ar[7]=v1.w;
        #pragma unroll
        for (int jj = 0; jj < 8; jj++)
            cpa16(bdst0 + jj * (4 * BP * 4), bsrc0 + (size_t)jj * 4 * MD);
        CPA_COMMIT();
        #pragma unroll
        for (int jj = 0; jj < 8; jj++)
            Asb[(size_t)arow * AP + apart * 8 + jj] = tf32f(ar[jj]);
        CPA_WAIT0();
    }
    __syncthreads();

    #pragma unroll 1
    for (int kc = 0; kc < 8; kc++) {
        const int cur = kc & 1, nxt = cur ^ 1;
        if (kc < 7) {
            #pragma unroll
            for (int jj = 0; jj < 8; jj++)
                cpa16(bdst0 + nxt * bbuf + jj * (4 * BP * 4),
                      bsrc0 + (size_t)(kc + 1) * 32 * MD + (size_t)jj * 4 * MD);
            CPA_COMMIT();
            float4 v0 = *(const float4*)(xrow + (kc + 1) * 32);
            float4 v1 = *(const float4*)(xrow + (kc + 1) * 32 + 4);
            ar[0]=v0.x; ar[1]=v0.y; ar[2]=v0.z; ar[3]=v0.w;
            ar[4]=v1.x; ar[5]=v1.y; ar[6]=v1.z; ar[7]=v1.w;
        }
        const float* Ac = Asb + (size_t)cur * 64 * AP;
        const float* Bc = Bsb + (size_t)cur * 32 * BP;
        #pragma unroll
        for (int kb = 0; kb < 32; kb += 8) {
            uint32_t af[2][4];
            #pragma unroll
            for (int m = 0; m < 2; m++) {
                int r0 = mg * 32 + m * 16;
                af[m][0] = __float_as_uint(Ac[(r0 + g) * AP + kb + l]);
                af[m][1] = __float_as_uint(Ac[(r0 + g + 8) * AP + kb + l]);
                af[m][2] = __float_as_uint(Ac[(r0 + g) * AP + kb + l + 4]);
                af[m][3] = __float_as_uint(Ac[(r0 + g + 8) * AP + kb + l + 4]);
            }
            #pragma unroll
            for (int n = 0; n < 8; n++) {
                uint32_t bf[2];
                int nb = ng * 64 + n * 8 + g;
                bf[0] = __float_as_uint(Bc[(kb + l) * BP + nb]);
                bf[1] = __float_as_uint(Bc[(kb + l + 4) * BP + nb]);
                mma8(acc[0][n], af[0], bf);
                mma8(acc[1][n], af[1], bf);
            }
        }
        if (kc < 7) {
            float* An = Asb + (size_t)nxt * 64 * AP;
            #pragma unroll
            for (int jj = 0; jj < 8; jj++)
                An[(size_t)arow * AP + apart * 8 + jj] = tf32f(ar[jj]);
            CPA_WAIT0();
        }
        __syncthreads();
    }

    const float bl2v = b_l2[0];
    if (ng >= 2) {
        float p[4] = {0.f, 0.f, 0.f, 0.f};
        #pragma unroll
        for (int m = 0; m < 2; m++)
            #pragma unroll
            for (int n = 0; n < 8; n++) {
                int cb = (ng - 2) * 64 + n * 8 + 2 * l;
                float u0 = u_s[cb], u1 = u_s[cb + 1];
                float e0 = bel_s[cb], e1 = bel_s[cb + 1];
                p[m*2+0] += fmaxf(acc[m][n][0] + e0, 0.f) * u0 + fmaxf(acc[m][n][1] + e1, 0.f) * u1;
                p[m*2+1] += fmaxf(acc[m][n][2] + e0, 0.f) * u0 + fmaxf(acc[m][n][3] + e1, 0.f) * u1;
            }
        #pragma unroll
        for (int q = 0; q < 4; q++) {
            p[q] += __shfl_xor_sync(0xffffffffu, p[q], 1);
            p[q] += __shfl_xor_sync(0xffffffffu, p[q], 2);
        }
        if (l == 0) {
            lpart[(ng - 2) * 64 + mg * 32 + g]      = p[0];
            lpart[(ng - 2) * 64 + mg * 32 + g + 8]  = p[1];
            lpart[(ng - 2) * 64 + mg * 32 + 16 + g] = p[2];
            lpart[(ng - 2) * 64 + mg * 32 + 24 + g] = p[3];
        }
    } else {
        float* mst = Bsb;                  // [64][132]
        #pragma unroll
        for (int m = 0; m < 2; m++) {
            int r0 = mg * 32 + m * 16 + g;
            #pragma unroll
            for (int n = 0; n < 8; n++) {
                int cb = ng * 64 + n * 8 + 2 * l;
                mst[r0 * 132 + cb]           = acc[m][n][0];
                mst[r0 * 132 + cb + 1]       = acc[m][n][1];
                mst[(r0 + 8) * 132 + cb]     = acc[m][n][2];
                mst[(r0 + 8) * 132 + cb + 1] = acc[m][n][3];
            }
        }
    }
    __syncthreads();

    if (t < 64) {
        int ri2 = t >> 4, wi2 = t & 15;
        if (i0 + ri2 < V && w0 + wi2 < V)
            g_sA[(b * NN + i0 + ri2) * NN + w0 + wi2] = lpart[t] + lpart[64 + t] + bl2v;
    }
    {
        int row = t >> 2, part = t & 3;
        int ri2 = row >> 4, wi2 = row & 15;
        if (i0 + ri2 < V && w0 + wi2 < V) {
            const float* ap = g_anf + (size_t)(b * NN + w0 + wi2) * MD + part * 32;
            float* mp = g_mraw + (size_t)((b * NN + i0 + ri2) * NN + w0 + wi2) * MD + part * 32;
            const float* mst = Bsb + row * 132 + part * 32;
            #pragma unroll
            for (int jj = 0; jj < 8; jj++) {
                float4 m4 = *(const float4*)(mst + jj * 4);
                float4 a4 = *(const float4*)(ap + jj * 4);
                float4 e4 = *(const float4*)(&bem_s[part * 32 + jj * 4]);
                float4 v;
                v.x = fmaxf(m4.x + e4.x + a4.x, 0.f);
                v.y = fmaxf(m4.y + e4.y + a4.y, 0.f);
                v.z = fmaxf(m4.z + e4.z + a4.z, 0.f);
                v.w = fmaxf(m4.w + e4.w + a4.w, 0.f);
                *(float4*)(mp + jj * 4) = v;
            }
        }
    }
}

// ================= round kernel: chunked + cp.async, occupancy 3, fused msum on pass 2 =================
#define RBP 136
__global__ __launch_bounds__(256, 3) void k_round_mma(
    int pass,
    const int* __restrict__ hn, const int* __restrict__ on,
    const float* __restrict__ b_l1,
    const float* __restrict__ W_l2, const float* __restrict__ b_l2,
    float* __restrict__ out_adj)
{
    const int b  = blockIdx.z;
    const int V  = hn[b] + on[b];
    const int i0 = blockIdx.y * 4;
    const int w0 = blockIdx.x * 16;
    if (i0 >= V || w0 >= V) return;

    const float* sprev = (pass == 1) ? g_sA : g_sB;
    float*       snext = (pass == 1) ? g_sB : g_sA;

    __shared__ float As[2][64][AP];        // 18.4 KB
    __shared__ float Bs[2][32][RBP];       // 34.8 KB
    __shared__ float lpart[4][64];
    __shared__ float gates[64];            // input gates, then reused for sig(s2)
    __shared__ float bl1_s[MD], u_s[MD];

    const int t    = threadIdx.x;
    const int wid  = t >> 5;
    const int lane = t & 31;
    const int g    = lane >> 2;
    const int l    = lane & 3;
    const int mg   = wid >> 2;
    const int ng   = wid & 3;

    if (t < 128) { bl1_s[t] = b_l1[t]; u_s[t] = W_l2[t]; }
    if (t < 64) {
        int ri = t >> 4, wi = t & 15;
        bool ok = (i0 + ri < V) && (w0 + wi < V);
        gates[t] = ok ? sigmoidf_(sprev[(b * NN + w0 + wi) * NN + i0 + ri]) : 0.f;
    }
    __syncthreads();

    const int arow  = t >> 2;
    const int apart = t & 3;
    const int ari = arow >> 4, awi = arow & 15;
    const float gv = gates[arow];
    const float* mrow = g_mraw + (size_t)((b * NN + w0 + awi) * NN + i0 + ari) * MD + apart * 8;

    uint32_t bdst[4];
    const float* bsrc[4];
    #pragma unroll
    for (int jj = 0; jj < 4; jj++) {
        int idx = jj * 256 + t;            // 0..1023
        int row = idx >> 5;                // 0..31
        int c4  = idx & 31;
        bdst[jj] = smem_u32(&Bs[0][row][c4 * 4]);
        bsrc[jj] = &g_Wl1c[(size_t)row * MD + c4 * 4];
    }
    const uint32_t bufB = (uint32_t)(32 * RBP * 4);

    float acc[2][4][4];
    #pragma unroll
    for (int m = 0; m < 2; m++)
        #pragma unroll
        for (int n = 0; n < 4; n++)
            #pragma unroll
            for (int q = 0; q < 4; q++) acc[m][n][q] = 0.f;

    float ar[8];
    #pragma unroll
    for (int jj = 0; jj < 8; jj++) ar[jj] = mrow[jj];
    #pragma unroll
    for (int jj = 0; jj < 4; jj++) cpa16(bdst[jj], bsrc[jj]);
    CPA_COMMIT();
    #pragma unroll
    for (int jj = 0; jj < 8; jj++) As[0][arow][apart * 8 + jj] = tf32f(ar[jj] * gv);
    CPA_WAIT0();
    __syncthreads();

    #pragma unroll 1
    for (int kc = 0; kc < 4; kc++) {
        const int cur = kc & 1, nxt = cur ^ 1;
        if (kc < 3) {
            #pragma unroll
            for (int jj = 0; jj < 4; jj++)
                cpa16(bdst[jj] + nxt * bufB, bsrc[jj] + (size_t)(kc + 1) * 32 * MD);
            CPA_COMMIT();
            #pragma unroll
            for (int jj = 0; jj < 8; jj++) ar[jj] = mrow[(kc + 1) * 32 + jj];
        }
        #pragma unroll
        for (int kb = 0; kb < 32; kb += 8) {
            uint32_t af[2][4];
            #pragma unroll
            for (int m = 0; m < 2; m++) {
                int r0 = mg * 32 + m * 16;
                af[m][0] = __float_as_uint(As[cur][r0 + g][kb + l]);
                af[m][1] = __float_as_uint(As[cur][r0 + g + 8][kb + l]);
                af[m][2] = __float_as_uint(As[cur][r0 + g][kb + l + 4]);
                af[m][3] = __float_as_uint(As[cur][r0 + g + 8][kb + l + 4]);
            }
            #pragma unroll
            for (int n = 0; n < 4; n++) {
                uint32_t bf[2];
                int nb = ng * 32 + n * 8 + g;
                bf[0] = __float_as_uint(Bs[cur][kb + l][nb]);
                bf[1] = __float_as_uint(Bs[cur][kb + l + 4][nb]);
                mma8(acc[0][n], af[0], bf);
                mma8(acc[1][n], af[1], bf);
            }
        }
        if (kc < 3) {
            #pragma unroll
            for (int jj = 0; jj < 8; jj++) As[nxt][arow][apart * 8 + jj] = tf32f(ar[jj] * gv);
            CPA_WAIT0();
        }
        __syncthreads();
    }

    {
        float p[4] = {0.f, 0.f, 0.f, 0.f};
        #pragma unroll
        for (int m = 0; m < 2; m++)
            #pragma unroll
            for (int n = 0; n < 4; n++) {
                int cb = ng * 32 + n * 8 + 2 * l;
                float u0 = u_s[cb], u1 = u_s[cb + 1];
                float e0 = bl1_s[cb], e1 = bl1_s[cb + 1];
                p[m*2+0] += fmaxf(acc[m][n][0] + e0, 0.f) * u0 + fmaxf(acc[m][n][1] + e1, 0.f) * u1;
                p[m*2+1] += fmaxf(acc[m][n][2] + e0, 0.f) * u0 + fmaxf(acc[m][n][3] + e1, 0.f) * u1;
            }
        #pragma unroll
        for (int q = 0; q < 4; q++) {
            p[q] += __shfl_xor_sync(0xffffffffu, p[q], 1);
            p[q] += __shfl_xor_sync(0xffffffffu, p[q], 2);
        }
        if (l == 0) {
            lpart[ng][mg * 32 + g]      = p[0];
            lpart[ng][mg * 32 + g + 8]  = p[1];
            lpart[ng][mg * 32 + 16 + g] = p[2];
            lpart[ng][mg * 32 + 24 + g] = p[3];
        }
    }
    __syncthreads();
    if (t < 64) {
        int ri2 = t >> 4, wi2 = t & 15;
        bool ok = (i0 + ri2 < V) && (w0 + wi2 < V);
        float sv = 0.f;
        if (ok) {
            int d = (b * NN + i0 + ri2) * NN + w0 + wi2;
            sv = (lpart[0][t] + lpart[1][t]) + (lpart[2][t] + lpart[3][t]) + b_l2[0];
            snext[d] = sv;
            if (out_adj) out_adj[d] = sv;
        }
        gates[t] = ok ? sigmoidf_(sv) : 0.f;   // reuse gates[] for sig(s_next)
    }

    // ---- fused m_sum on final pass ----
    if (out_adj) {
        __syncthreads();
        const int r = t >> 6;                  // 0..3 receiver row
        const int c = (t & 63) * 2;            // 2 contiguous cols
        if (i0 + r < V) {
            const float* mp2 = g_mraw + (size_t)((b * NN + i0 + r) * NN + w0) * MD + c;
            float s0 = 0.f, s1 = 0.f;
            #pragma unroll
            for (int wq = 0; wq < 16; wq++) {
                float gq = gates[r * 16 + wq];
                float2 mv = *(const float2*)(mp2 + (size_t)wq * MD);
                s0 = fmaf(gq, mv.x, s0);
                s1 = fmaf(gq, mv.y, s1);
            }
            float* dst = &g_msum[(size_t)(b * NN + i0 + r) * MD + c];
            atomicAdd(dst, s0);
            atomicAdd(dst + 1, s1);
        }
    }
}

// ---------------- GRU + readout, 4 nodes per block, labels split over blockIdx.z ----------------
__global__ __launch_bounds__(128) void k_gru(
    const int* __restrict__ hn, const int* __restrict__ on,
    const float* __restrict__ W_ih, const float* __restrict__ b_ih,
    const float* __restrict__ W_hh, const float* __restrict__ b_hh,
    const float* __restrict__ W_ro, const float* __restrict__ b_ro,
    float* __restrict__ out)
{
    const int b  = blockIdx.y;
    const int V  = hn[b] + on[b];
    const int i0 = blockIdx.x * 4;
    const int cb = blockIdx.z;             // 0..4: which 128-col label slab
    const int t  = threadIdx.x;

    __shared__ float ms[4][MD];
    __shared__ float hsn[4][MD];
    __shared__ float hnew[4][MD];

    #pragma unroll
    for (int n = 0; n < 4; n++) {
        ms[n][t]  = g_msum[(size_t)(b * NN + i0 + n) * MD + t];
        hsn[n][t] = g_nf[(size_t)(b * NN + i0 + n) * MD + t];
    }
    __syncthreads();

    float air[4], aiz[4], ain[4], ahr[4], ahz[4], ahn[4];
    {
        float bir = b_ih[t], biz = b_ih[128 + t], bin_ = b_ih[256 + t];
        float bhr = b_hh[t], bhz = b_hh[128 + t], bhn = b_hh[256 + t];
        #pragma unroll
        for (int n = 0; n < 4; n++) {
            air[n] = bir; aiz[n] = biz; ain[n] = bin_;
            ahr[n] = bhr; ahz[n] = bhz; ahn[n] = bhn;
        }
    }
    #pragma unroll 2
    for (int k = 0; k < MD; k++) {
        float wr = W_ih[k * 384 + t];
        float wz = W_ih[k * 384 + 128 + t];
        float wn = W_ih[k * 384 + 256 + t];
        float vr = W_hh[k * 384 + t];
        float vz = W_hh[k * 384 + 128 + t];
        float vn = W_hh[k * 384 + 256 + t];
        #pragma unroll
        for (int n = 0; n < 4; n++) {
            float xv = ms[n][k], hv = hsn[n][k];
            air[n] = fmaf(xv, wr, air[n]);
            aiz[n] = fmaf(xv, wz, aiz[n]);
            ain[n] = fmaf(xv, wn, ain[n]);
            ahr[n] = fmaf(hv, vr, ahr[n]);
            ahz[n] = fmaf(hv, vz, ahz[n]);
            ahn[n] = fmaf(hv, vn, ahn[n]);
        }
    }
    #pragma unroll
    for (int n = 0; n < 4; n++) {
        float r   = sigmoidf_(air[n] + ahr[n]);
        float z   = sigmoidf_(aiz[n] + ahz[n]);
        float nn_ = tanhf(ain[n] + r * ahn[n]);
        hnew[n][t] = (1.f - z) * nn_ + z * hsn[n][t];
    }
    __syncthreads();

    // this block writes label columns [cb*128, cb*128+128)
    float* lab = out + (size_t)BN * NN * NN;
    int c = cb * 128 + t;
    if (c < CLS) {
        float lacc[4];
        #pragma unroll
        for (int n = 0; n < 4; n++) lacc[n] = 0.f;
        #pragma unroll 4
        for (int k = 0; k < MD; k++) {
            float wv = W_ro[k * CLS + c];
            #pragma unroll
            for (int n = 0; n < 4; n++) lacc[n] = fmaf(hnew[n][k], wv, lacc[n]);
        }
        float bv = b_ro[c];
        #pragma unroll
        for (int n = 0; n < 4; n++) {
            int i = i0 + n;
            float v = (i < V) ? (lacc[n] + bv) : 0.f;
            lab[(size_t)(b * NN + i) * CLS + c] = v;
        }
    }
}

// ---------------- launcher ----------------
extern "C" void kernel_launch(void* const* d_in, const int* in_sizes, int n_in,
                              void* d_out, int out_size)
{
    const float* edge_features = (const float*)d_in[0];
    const float* node_features = (const float*)d_in[1];
    const int*   human = (const int*)d_in[4];
    const int*   obj   = (const int*)d_in[5];
    const float* W_er  = (const float*)d_in[6];
    const float* b_er  = (const float*)d_in[7];
    const float* W_nr  = (const float*)d_in[8];
    const float* b_nr  = (const float*)d_in[9];
    const float* W_l1  = (const float*)d_in[10];
    const float* b_l1  = (const float*)d_in[11];
    const float* W_l2  = (const float*)d_in[12];
    const float* b_l2  = (const float*)d_in[13];
    const float* W_msg = (const float*)d_in[14];
    const float* b_msg = (const float*)d_in[15];
    const float* W_ih  = (const float*)d_in[16];
    const float* b_ih  = (const float*)d_in[17];
    const float* W_hh  = (const float*)d_in[18];
    const float* b_hh  = (const float*)d_in[19];
    const float* W_ro  = (const float*)d_in[20];
    const float* b_ro  = (const float*)d_in[21];
    float* out = (float*)d_out;

    cudaFuncSetAttribute(k_edge_mma, cudaFuncAttributeMaxDynamicSharedMemorySize, ED_SMEM);

    k_prep<<<1410, 256>>>(out, node_features, W_er, b_er, W_nr, b_nr, W_msg, b_msg, W_l1, b_l1);

    dim3 eg(NN / 16, NN / 4, BN);    // 16 x 64 x 4 = 4096 CTAs, 64 edges each
    k_edge_mma<<<eg, 256, ED_SMEM>>>(edge_features, human, obj, W_l2, b_l2);
    k_round_mma<<<eg, 256>>>(1, human, obj, b_l1, W_l2, b_l2, nullptr);
    k_round_mma<<<eg, 256>>>(2, human, obj, b_l1, W_l2, b_l2, out);   // + fused m_sum

    k_gru<<<dim3(NN / 4, BN, 5), 128>>>(human, obj, W_ih, b_ih, W_hh, b_hh, W_ro, b_ro, out);
}